// round 13
// baseline (speedup 1.0000x reference)
#include <cuda_runtime.h>
#include <cstddef>
#include <cstdint>

// ---------------- problem constants ----------------
constexpr int BWIN = 4096;
constexpr int NTOK = 64;
constexpr int CDIM = 256;
constexpr int HEADS = 8;
constexpr int MROWS = BWIN * NTOK;          // 262144
constexpr float SCALE = 0.1767766952966369f; // 32^-0.5

// ---------------- scratch ----------------
// q/k: [bh][n][32] k-permuted tf32.  v: [bh][d][64] n-permuted tf32 (transposed).
__device__ float g_q[BWIN * HEADS * NTOK * 32];
__device__ float g_k[BWIN * HEADS * NTOK * 32];
__device__ float g_v[BWIN * HEADS * NTOK * 32];
__device__ float g_o[MROWS * CDIM];         // tf32-rounded fp32 [m][256]
__device__ float g_wt[1024 * CDIM];         // RNA-rounded weights
__device__ float g_bias8[HEADS * 64 * 64];

// ---------------- helpers ----------------
__device__ __forceinline__ float to_tf32(float x) {
    unsigned r;
    asm("cvt.rna.tf32.f32 %0, %1;" : "=r"(r) : "f"(x));
    return __uint_as_float(r);
}
__device__ __forceinline__ unsigned f2u(float x) { return __float_as_uint(x); }
// HMMA truncates low 13 mantissa bits (RZ); +0x1000 first == round-to-nearest.
__device__ __forceinline__ unsigned rna(float x) { return __float_as_uint(x) + 0x1000u; }

__device__ __forceinline__ void mma_tf32(float* c, unsigned a0, unsigned a1,
                                         unsigned a2, unsigned a3,
                                         unsigned b0, unsigned b1) {
    asm volatile(
        "mma.sync.aligned.m16n8k8.row.col.f32.tf32.tf32.f32 "
        "{%0,%1,%2,%3}, {%4,%5,%6,%7}, {%8,%9}, {%0,%1,%2,%3};"
        : "+f"(c[0]), "+f"(c[1]), "+f"(c[2]), "+f"(c[3])
        : "r"(a0), "r"(a1), "r"(a2), "r"(a3), "r"(b0), "r"(b1));
}

__device__ __forceinline__ void cp16(uint32_t dst, const void* src) {
    asm volatile("cp.async.cg.shared.global [%0], [%1], 16;" :: "r"(dst), "l"(src) : "memory");
}
__device__ __forceinline__ void cp_commit() {
    asm volatile("cp.async.commit_group;" ::: "memory");
}
template <int N>
__device__ __forceinline__ void cp_wait() {
    asm volatile("cp.async.wait_group %0;" :: "n"(N) : "memory");
}

// ---------------- round weights (RNA tf32) into g_wt ----------------
__global__ void __launch_bounds__(256) round_w(
    const float* __restrict__ Wq, const float* __restrict__ Wkv,
    const float* __restrict__ Wp)
{
    int fi = blockIdx.x * 256 + threadIdx.x;    // float4 index, 0..65535
    int row = fi >> 6;
    int col4 = fi & 63;
    const float* src;
    if (row < 256) src = Wq + ((size_t)row * 64 + col4) * 4;
    else if (row < 768) src = Wkv + ((size_t)(row - 256) * 64 + col4) * 4;
    else src = Wp + ((size_t)(row - 768) * 64 + col4) * 4;
    float4 v = *(const float4*)src;
    *((float4*)g_wt + fi) =
        make_float4(to_tf32(v.x), to_tf32(v.y), to_tf32(v.z), to_tf32(v.w));
}

// ---------------- expand relative-position bias to [h][i][j] ----------------
__global__ void __launch_bounds__(256) bias8_kernel(const float* __restrict__ bias_table)
{
    int idx = blockIdx.x * 256 + threadIdx.x;
    int h = idx >> 12;
    int ij = idx & 4095;
    int i = ij >> 6, j = ij & 63;
    int ih = i >> 3, iw = i & 7, jh = j >> 3, jw = j & 7;
    int ridx = (ih - jh + 7) * 15 + (iw - jw + 7);
    g_bias8[idx] = bias_table[ridx * 8 + h];
}

// ---------------- TF32 tensor GEMM, cp.async 3-stage + SMEM-restaged epilogue ----------------
// CTA tile 128x128xK256; 8 warps (4m x 2n), warp tile 32x64.
// MODE 0: A=x; W rows c0.. of g_wt; restage -> coalesced float4 scatter to g_q/g_k/g_v.
// MODE 1: A=g_o; W rows 768+c0..; restage -> coalesced float4 to outP.
template <int MODE>
__global__ void __launch_bounds__(256, 2) mma_gemm(
    const float* __restrict__ A_in,
    const float* __restrict__ b0v, const float* __restrict__ b1v,
    float* __restrict__ outP)
{
    __shared__ char smem_raw[49152];           // 3-stage pipeline (48KB) / epilogue stage (34KB)
    float4* As4base = (float4*)smem_raw;                    // [3][512]
    float4* Bs4base = (float4*)(smem_raw + 24576);          // [3][512]
    float* stage = (float*)smem_raw;                        // [128][66]
    constexpr int SSTR = 66;

    const float* A = (MODE == 0) ? A_in : g_o;
    const int c0 = blockIdx.x * 128;
    const int m0 = blockIdx.y * 128;
    const float* Wsrc = g_wt + (size_t)((MODE == 0 ? 0 : 768) + c0) * CDIM;

    const int t = threadIdx.x;
    const int wid = t >> 5, lane = t & 31;
    const int wm = wid & 3, wn = wid >> 2;
    const int gid = lane >> 2, tig = lane & 3;
    const int mrow = wm * 32, ncol = wn * 64;

    float c[2][8][4];
#pragma unroll
    for (int mt = 0; mt < 2; mt++)
#pragma unroll
        for (int nt = 0; nt < 8; nt++)
#pragma unroll
            for (int i = 0; i < 4; i++) c[mt][nt][i] = 0.f;

    // ---- cp.async mapping ----
    const int arow = t >> 2;
    const int ac = t & 3;
    const int apc  = ac ^ ((arow >> 1) & 3);
    const int arowB = arow + 64;
    const int apcB = ac ^ ((arowB >> 1) & 3);

    const uint32_t dA0 = (uint32_t)__cvta_generic_to_shared(&As4base[arow * 4 + apc]);
    const uint32_t dA1 = (uint32_t)__cvta_generic_to_shared(&As4base[arowB * 4 + apcB]);
    const uint32_t dB0 = (uint32_t)__cvta_generic_to_shared(&Bs4base[arow * 4 + apc]);
    const uint32_t dB1 = (uint32_t)__cvta_generic_to_shared(&Bs4base[arowB * 4 + apcB]);
    constexpr uint32_t STRIDE = 128 * 4 * 16;   // 8 KB per stage

    const float* srcA0 = A + (size_t)(m0 + arow) * CDIM + ac * 4;
    const float* srcA1 = A + (size_t)(m0 + arow + 64) * CDIM + ac * 4;
    const float* srcB0 = Wsrc + (size_t)arow * CDIM + ac * 4;
    const float* srcB1 = Wsrc + (size_t)(arow + 64) * CDIM + ac * 4;

    auto issue = [&](int kt, int s) {
        cp16(dA0 + s * STRIDE, srcA0 + kt * 16);
        cp16(dA1 + s * STRIDE, srcA1 + kt * 16);
        cp16(dB0 + s * STRIDE, srcB0 + kt * 16);
        cp16(dB1 + s * STRIDE, srcB1 + kt * 16);
        cp_commit();
    };

    // ---- fragment load indices (float4 units) ----
    int aIdx[2][2], bIdx[8];
#pragma unroll
    for (int mt = 0; mt < 2; mt++) {
        int r0 = mrow + mt * 16 + gid;
        int r1 = r0 + 8;
        aIdx[mt][0] = r0 * 4 + (tig ^ ((r0 >> 1) & 3));
        aIdx[mt][1] = r1 * 4 + (tig ^ ((r1 >> 1) & 3));
    }
#pragma unroll
    for (int nt = 0; nt < 8; nt++) {
        int nb = ncol + nt * 8 + gid;
        bIdx[nt] = nb * 4 + (tig ^ ((nb >> 1) & 3));
    }

    issue(0, 0);
    issue(1, 1);

#pragma unroll
    for (int kt = 0; kt < 16; kt++) {
        const int buf = kt % 3;
        cp_wait<1>();
        __syncthreads();

        {
            const float4* as = As4base + buf * 512;
            const float4* bs = Bs4base + buf * 512;
            unsigned au[2][2][4];
#pragma unroll
            for (int mt = 0; mt < 2; mt++) {
#pragma unroll
                for (int half = 0; half < 2; half++) {
                    float4 v = as[aIdx[mt][half]];
                    au[mt][half][0] = rna(v.x);
                    au[mt][half][1] = rna(v.y);
                    au[mt][half][2] = rna(v.z);
                    au[mt][half][3] = rna(v.w);
                }
            }
#pragma unroll
            for (int half = 0; half < 2; half++) {
                float4 b4[4];
#pragma unroll
                for (int j = 0; j < 4; j++) b4[j] = bs[bIdx[half * 4 + j]];
#pragma unroll
                for (int mt = 0; mt < 2; mt++)
#pragma unroll
                    for (int j = 0; j < 4; j++) {
                        float* cc = c[mt][half * 4 + j];
                        mma_tf32(cc,
                                 au[mt][0][0], au[mt][1][0],
                                 au[mt][0][1], au[mt][1][1],
                                 f2u(b4[j].x), f2u(b4[j].y));
                        mma_tf32(cc,
                                 au[mt][0][2], au[mt][1][2],
                                 au[mt][0][3], au[mt][1][3],
                                 f2u(b4[j].z), f2u(b4[j].w));
                    }
            }
        }
        __syncthreads();
        if (kt + 2 < 16) issue(kt + 2, (kt + 2) % 3);
    }

    // ---------------- epilogue: restage 64-col halves, coalesced stores ----------------
#pragma unroll 1
    for (int pass = 0; pass < 2; pass++) {
        __syncthreads();   // SMEM reuse: prior phase fully done
        if (wn == pass) {  // this warp's columns belong to this pass
#pragma unroll
            for (int nt = 0; nt < 8; nt++) {
                int col = nt * 8 + 2 * tig;            // 0..63 within pass
                int cg = c0 + pass * 64 + col;
                float bias0, bias1;
                if (MODE == 1) { bias0 = b0v[cg]; bias1 = b0v[cg + 1]; }
                else if (cg < 256) { bias0 = b0v[cg]; bias1 = b0v[cg + 1]; }
                else { bias0 = b1v[cg - 256]; bias1 = b1v[cg - 255]; }
#pragma unroll
                for (int mt = 0; mt < 2; mt++)
#pragma unroll
                    for (int rr = 0; rr < 2; rr++) {
                        int rloc = mrow + mt * 16 + gid + rr * 8;
                        stage[rloc * SSTR + col]     = c[mt][nt][rr * 2 + 0] + bias0;
                        stage[rloc * SSTR + col + 1] = c[mt][nt][rr * 2 + 1] + bias1;
                    }
            }
        }
        __syncthreads();

        const int cg0 = c0 + pass * 64;
        if (MODE == 1) {
            // 128 rows x 16 float4
#pragma unroll
            for (int i = 0; i < 8; i++) {
                int u = t + i * 256;           // 0..2047
                int row = u >> 4, f4 = u & 15;
                const float* s = &stage[row * SSTR + f4 * 4];
                float4 v = make_float4(s[0], s[1], s[2], s[3]);
                *(float4*)(outP + (size_t)(m0 + row) * CDIM + cg0 + f4 * 4) = v;
            }
        } else {
#pragma unroll 1
            for (int hb = 0; hb < 2; hb++) {
                const int cgB = cg0 + hb * 32;
                const int colbase = hb * 32;
                if (cgB < 512) {
                    float* base = (cgB < 256) ? g_q : g_k;
                    const float scl = (cgB < 256) ? SCALE : 1.0f;
                    const int hh = (cgB & 255) >> 5;
                    // 128 rows x 8 float4 (k-perm gather from stage)
#pragma unroll
                    for (int i = 0; i < 4; i++) {
                        int u = t + i * 256;     // 0..1023
                        int row = u >> 3, f4 = u & 7;
                        int a = f4 >> 2, b2 = f4 & 3;
                        const float* s = &stage[row * SSTR + colbase + 16 * a + b2];
                        float4 v;
                        v.x = to_tf32(s[0]  * scl);
                        v.y = to_tf32(s[4]  * scl);
                        v.z = to_tf32(s[8]  * scl);
                        v.w = to_tf32(s[12] * scl);
                        int m = m0 + row;
                        int b = m >> 6, n = m & 63;
                        *(float4*)(base + ((size_t)(b * 8 + hh)) * 2048 + n * 32 + f4 * 4) = v;
                    }
                } else {
                    const int hh = (cgB - 512) >> 5;
                    // 2 windows x 32 d x 16 float4 (n-perm gather, transposed)
#pragma unroll
                    for (int i = 0; i < 4; i++) {
                        int u = t + i * 256;     // 0..1023
                        int win = u >> 9;
                        int dd = (u >> 4) & 31;
                        int f4 = u & 15;
                        int g = f4 >> 2, c2 = f4 & 3;
                        int nbase = win * 64 + 16 * g + c2;
                        const float* s = &stage[colbase + dd];
                        float4 v;
                        v.x = to_tf32(s[(nbase + 0)  * SSTR]);
                        v.y = to_tf32(s[(nbase + 4)  * SSTR]);
                        v.z = to_tf32(s[(nbase + 8)  * SSTR]);
                        v.w = to_tf32(s[(nbase + 12) * SSTR]);
                        int b = (m0 >> 6) + win;
                        *(float4*)(g_v + ((size_t)(b * 8 + hh)) * 2048 + dd * 64 + f4 * 4) = v;
                    }
                }
            }
        }
    }
}

// ---------------- tensor-core attention per (window, head) ----------------
__global__ void __launch_bounds__(128) attn_kernel(const float* __restrict__ mask)
{
    const int bh = blockIdx.x;
    const int b  = bh >> 3;
    const int h  = bh & 7;
    const int w  = b & 1023;

    const int t = threadIdx.x;
    const int wid = t >> 5, lane = t & 31;
    const int gid = lane >> 2, tig = lane & 3;
    const int i0 = wid * 16 + gid;
    const int i1 = i0 + 8;

    const float* qg = g_q + (size_t)bh * 2048;
    const float* kg = g_k + (size_t)bh * 2048;
    const float* vg = g_v + (size_t)bh * 2048;

    float4 qa00 = *(const float4*)(qg + i0 * 32 + tig * 4);
    float4 qa01 = *(const float4*)(qg + i0 * 32 + 16 + tig * 4);
    float4 qa10 = *(const float4*)(qg + i1 * 32 + tig * 4);
    float4 qa11 = *(const float4*)(qg + i1 * 32 + 16 + tig * 4);

    float c[8][4];
#pragma unroll
    for (int nt = 0; nt < 8; nt++) {
        c[nt][0] = c[nt][1] = c[nt][2] = c[nt][3] = 0.f;
        const float* krow = kg + (8 * nt + gid) * 32;
        float4 kb0 = *(const float4*)(krow + tig * 4);
        float4 kb1 = *(const float4*)(krow + 16 + tig * 4);
        mma_tf32(c[nt], f2u(qa00.x), f2u(qa10.x), f2u(qa00.y), f2u(qa10.y), f2u(kb0.x), f2u(kb0.y));
        mma_tf32(c[nt], f2u(qa00.z), f2u(qa10.z), f2u(qa00.w), f2u(qa10.w), f2u(kb0.z), f2u(kb0.w));
        mma_tf32(c[nt], f2u(qa01.x), f2u(qa11.x), f2u(qa01.y), f2u(qa11.y), f2u(kb1.x), f2u(kb1.y));
        mma_tf32(c[nt], f2u(qa01.z), f2u(qa11.z), f2u(qa01.w), f2u(qa11.w), f2u(kb1.z), f2u(kb1.w));
    }

    const float* mrow = mask + (size_t)w * 4096;
    const float* brow = g_bias8 + h * 4096;
    float mx0 = -1e30f, mx1 = -1e30f;
#pragma unroll
    for (int nt = 0; nt < 8; nt++) {
        int coff = nt * 8 + 2 * tig;
        float2 m0 = *(const float2*)(mrow + i0 * 64 + coff);
        float2 b0 = *(const float2*)(brow + i0 * 64 + coff);
        float2 m1 = *(const float2*)(mrow + i1 * 64 + coff);
        float2 b1 = *(const float2*)(brow + i1 * 64 + coff);
        c[nt][0] += m0.x + b0.x;
        c[nt][1] += m0.y + b0.y;
        c[nt][2] += m1.x + b1.x;
        c[nt][3] += m1.y + b1.y;
        mx0 = fmaxf(mx0, fmaxf(c[nt][0], c[nt][1]));
        mx1 = fmaxf(mx1, fmaxf(c[nt][2], c[nt][3]));
    }
    mx0 = fmaxf(mx0, __shfl_xor_sync(~0u, mx0, 1));
    mx0 = fmaxf(mx0, __shfl_xor_sync(~0u, mx0, 2));
    mx1 = fmaxf(mx1, __shfl_xor_sync(~0u, mx1, 1));
    mx1 = fmaxf(mx1, __shfl_xor_sync(~0u, mx1, 2));

    float s0 = 0.f, s1 = 0.f;
#pragma unroll
    for (int nt = 0; nt < 8; nt++) {
        c[nt][0] = __expf(c[nt][0] - mx0);
        c[nt][1] = __expf(c[nt][1] - mx0);
        c[nt][2] = __expf(c[nt][2] - mx1);
        c[nt][3] = __expf(c[nt][3] - mx1);
        s0 += c[nt][0] + c[nt][1];
        s1 += c[nt][2] + c[nt][3];
    }
    s0 += __shfl_xor_sync(~0u, s0, 1);
    s0 += __shfl_xor_sync(~0u, s0, 2);
    s1 += __shfl_xor_sync(~0u, s1, 1);
    s1 += __shfl_xor_sync(~0u, s1, 2);
    float r0 = 1.0f / s0, r1 = 1.0f / s1;
#pragma unroll
    for (int nt = 0; nt < 8; nt++) {
        c[nt][0] = to_tf32(c[nt][0] * r0);
        c[nt][1] = to_tf32(c[nt][1] * r0);
        c[nt][2] = to_tf32(c[nt][2] * r1);
        c[nt][3] = to_tf32(c[nt][3] * r1);
    }

    unsigned a[8][4];
    const int src1 = (gid << 2) + (tig >> 1);
    const int src2 = src1 + 2;
    const bool odd = (tig & 1);
#pragma unroll
    for (int kt = 0; kt < 8; kt++) {
        float p0 = __shfl_sync(~0u, c[kt][0], src1);
        float p1 = __shfl_sync(~0u, c[kt][1], src1);
        float p2 = __shfl_sync(~0u, c[kt][2], src1);
        float p3 = __shfl_sync(~0u, c[kt][3], src1);
        float q0 = __shfl_sync(~0u, c[kt][0], src2);
        float q1 = __shfl_sync(~0u, c[kt][1], src2);
        float q2 = __shfl_sync(~0u, c[kt][2], src2);
        float q3 = __shfl_sync(~0u, c[kt][3], src2);
        a[kt][0] = f2u(odd ? p1 : p0);
        a[kt][1] = f2u(odd ? p3 : p2);
        a[kt][2] = f2u(odd ? q1 : q0);
        a[kt][3] = f2u(odd ? q3 : q2);
    }

    float co[4][4];
#pragma unroll
    for (int nt = 0; nt < 4; nt++)
        co[nt][0] = co[nt][1] = co[nt][2] = co[nt][3] = 0.f;

#pragma unroll
    for (int g = 0; g < 4; g++) {
        float4 vb[4];
#pragma unroll
        for (int nt = 0; nt < 4; nt++)
            vb[nt] = *(const float4*)(vg + (8 * nt + gid) * 64 + g * 16 + tig * 4);
        int kt0 = 2 * g;
#pragma unroll
        for (int nt = 0; nt < 4; nt++) {
            mma_tf32(co[nt], a[kt0][0], a[kt0][1], a[kt0][2], a[kt0][3],
                     f2u(vb[nt].x), f2u(vb[nt].y));
            mma_tf32(co[nt], a[kt0 + 1][0], a[kt0 + 1][1], a[kt0 + 1][2], a[kt0 + 1][3],
                     f2u(vb[nt].z), f2u(vb[nt].w));
        }
    }

    // store O tf32-rounded: g_o[m][h*32 + d]
    size_t orow0 = ((size_t)(b * 64 + i0)) * CDIM + h * 32;
    size_t orow1 = ((size_t)(b * 64 + i1)) * CDIM + h * 32;
#pragma unroll
    for (int nt = 0; nt < 4; nt++) {
        int col = nt * 8 + 2 * tig;
        *(float2*)&g_o[orow0 + col] = make_float2(to_tf32(co[nt][0]), to_tf32(co[nt][1]));
        *(float2*)&g_o[orow1 + col] = make_float2(to_tf32(co[nt][2]), to_tf32(co[nt][3]));
    }
}

// ---------------- launch ----------------
extern "C" void kernel_launch(void* const* d_in, const int* in_sizes, int n_in,
                              void* d_out, int out_size)
{
    const float* x          = (const float*)d_in[0];
    const float* mask       = (const float*)d_in[1];
    const float* Wq         = (const float*)d_in[2];
    const float* bq         = (const float*)d_in[3];
    const float* Wkv        = (const float*)d_in[4];
    const float* bkv        = (const float*)d_in[5];
    const float* bias_table = (const float*)d_in[6];
    const float* Wp         = (const float*)d_in[7];
    const float* bp         = (const float*)d_in[8];
    float* out = (float*)d_out;

    round_w<<<256, 256>>>(Wq, Wkv, Wp);
    bias8_kernel<<<128, 256>>>(bias_table);
    mma_gemm<0><<<dim3(6, MROWS / 128), 256>>>(x, bq, bkv, nullptr);
    attn_kernel<<<BWIN * HEADS, 128>>>(mask);
    mma_gemm<1><<<dim3(2, MROWS / 128), 256>>>(nullptr, bp, nullptr, out);
}

// round 15
// speedup vs baseline: 1.0225x; 1.0225x over previous
#include <cuda_runtime.h>
#include <cstddef>
#include <cstdint>

// ---------------- problem constants ----------------
constexpr int BWIN = 4096;
constexpr int NTOK = 64;
constexpr int CDIM = 256;
constexpr int HEADS = 8;
constexpr int MROWS = BWIN * NTOK;          // 262144
constexpr float SCALE = 0.1767766952966369f; // 32^-0.5

// ---------------- scratch ----------------
// q/k: [bh][n][32] k-permuted tf32.  v: [bh][d][64] n-permuted tf32 (transposed).
__device__ float g_q[BWIN * HEADS * NTOK * 32];
__device__ float g_k[BWIN * HEADS * NTOK * 32];
__device__ float g_v[BWIN * HEADS * NTOK * 32];
__device__ float g_o[MROWS * CDIM];         // tf32-rounded fp32 [m][256]
__device__ float g_wt[1024 * CDIM];         // RNA-rounded weights
__device__ float g_bias8[HEADS * 64 * 64];

// ---------------- helpers ----------------
__device__ __forceinline__ float to_tf32(float x) {
    unsigned r;
    asm("cvt.rna.tf32.f32 %0, %1;" : "=r"(r) : "f"(x));
    return __uint_as_float(r);
}
__device__ __forceinline__ unsigned f2u(float x) { return __float_as_uint(x); }
// HMMA truncates low 13 mantissa bits (RZ); +0x1000 first == round-to-nearest.
__device__ __forceinline__ unsigned rna(float x) { return __float_as_uint(x) + 0x1000u; }

__device__ __forceinline__ void mma_tf32(float* c, unsigned a0, unsigned a1,
                                         unsigned a2, unsigned a3,
                                         unsigned b0, unsigned b1) {
    asm volatile(
        "mma.sync.aligned.m16n8k8.row.col.f32.tf32.tf32.f32 "
        "{%0,%1,%2,%3}, {%4,%5,%6,%7}, {%8,%9}, {%0,%1,%2,%3};"
        : "+f"(c[0]), "+f"(c[1]), "+f"(c[2]), "+f"(c[3])
        : "r"(a0), "r"(a1), "r"(a2), "r"(a3), "r"(b0), "r"(b1));
}

__device__ __forceinline__ void cp16(uint32_t dst, const void* src) {
    asm volatile("cp.async.cg.shared.global [%0], [%1], 16;" :: "r"(dst), "l"(src) : "memory");
}
__device__ __forceinline__ void cp_commit() {
    asm volatile("cp.async.commit_group;" ::: "memory");
}
template <int N>
__device__ __forceinline__ void cp_wait() {
    asm volatile("cp.async.wait_group %0;" :: "n"(N) : "memory");
}

// ---------------- round weights (RNA tf32) into g_wt ----------------
__global__ void __launch_bounds__(256) round_w(
    const float* __restrict__ Wq, const float* __restrict__ Wkv,
    const float* __restrict__ Wp)
{
    int fi = blockIdx.x * 256 + threadIdx.x;    // float4 index, 0..65535
    int row = fi >> 6;
    int col4 = fi & 63;
    const float* src;
    if (row < 256) src = Wq + ((size_t)row * 64 + col4) * 4;
    else if (row < 768) src = Wkv + ((size_t)(row - 256) * 64 + col4) * 4;
    else src = Wp + ((size_t)(row - 768) * 64 + col4) * 4;
    float4 v = *(const float4*)src;
    *((float4*)g_wt + fi) =
        make_float4(to_tf32(v.x), to_tf32(v.y), to_tf32(v.z), to_tf32(v.w));
}

// ---------------- expand relative-position bias to [h][i][j] ----------------
__global__ void __launch_bounds__(256) bias8_kernel(const float* __restrict__ bias_table)
{
    int idx = blockIdx.x * 256 + threadIdx.x;
    int h = idx >> 12;
    int ij = idx & 4095;
    int i = ij >> 6, j = ij & 63;
    int ih = i >> 3, iw = i & 7, jh = j >> 3, jw = j & 7;
    int ridx = (ih - jh + 7) * 15 + (iw - jw + 7);
    g_bias8[idx] = bias_table[ridx * 8 + h];
}

// ---------------- TF32 tensor GEMM, cp.async 3-stage (R12 epilogue) ----------------
// CTA tile 128x128xK256; 8 warps (4m x 2n), warp tile 32x64.
// A fragments RNA-rounded in registers (+0x1000); W pre-rounded in g_wt.
// MODE 0: A=x; scatter -> g_q/g_k/g_v.   MODE 1: A=g_o -> outP.
template <int MODE>
__global__ void __launch_bounds__(256, 2) mma_gemm(
    const float* __restrict__ A_in,
    const float* __restrict__ b0v, const float* __restrict__ b1v,
    float* __restrict__ outP)
{
    constexpr int STAGES = 3;
    __shared__ float4 As4[STAGES][128 * 4];
    __shared__ float4 Bs4[STAGES][128 * 4];

    const float* A = (MODE == 0) ? A_in : g_o;
    const int c0 = blockIdx.x * 128;
    const int m0 = blockIdx.y * 128;
    const float* Wsrc = g_wt + (size_t)((MODE == 0 ? 0 : 768) + c0) * CDIM;

    const int t = threadIdx.x;
    const int wid = t >> 5, lane = t & 31;
    const int wm = wid & 3, wn = wid >> 2;
    const int gid = lane >> 2, tig = lane & 3;
    const int mrow = wm * 32, ncol = wn * 64;

    float c[2][8][4];
#pragma unroll
    for (int mt = 0; mt < 2; mt++)
#pragma unroll
        for (int nt = 0; nt < 8; nt++)
#pragma unroll
            for (int i = 0; i < 4; i++) c[mt][nt][i] = 0.f;

    const int arow = t >> 2;
    const int ac = t & 3;
    const int apc  = ac ^ ((arow >> 1) & 3);
    const int arowB = arow + 64;
    const int apcB = ac ^ ((arowB >> 1) & 3);

    const uint32_t dA0 = (uint32_t)__cvta_generic_to_shared(&As4[0][arow * 4 + apc]);
    const uint32_t dA1 = (uint32_t)__cvta_generic_to_shared(&As4[0][arowB * 4 + apcB]);
    const uint32_t dB0 = (uint32_t)__cvta_generic_to_shared(&Bs4[0][arow * 4 + apc]);
    const uint32_t dB1 = (uint32_t)__cvta_generic_to_shared(&Bs4[0][arowB * 4 + apcB]);
    constexpr uint32_t STRIDE = 128 * 4 * 16;   // 8 KB per stage

    const float* srcA0 = A + (size_t)(m0 + arow) * CDIM + ac * 4;
    const float* srcA1 = A + (size_t)(m0 + arow + 64) * CDIM + ac * 4;
    const float* srcB0 = Wsrc + (size_t)arow * CDIM + ac * 4;
    const float* srcB1 = Wsrc + (size_t)(arow + 64) * CDIM + ac * 4;

    auto issue = [&](int kt, int s) {
        cp16(dA0 + s * STRIDE, srcA0 + kt * 16);
        cp16(dA1 + s * STRIDE, srcA1 + kt * 16);
        cp16(dB0 + s * STRIDE, srcB0 + kt * 16);
        cp16(dB1 + s * STRIDE, srcB1 + kt * 16);
        cp_commit();
    };

    int aIdx[2][2], bIdx[8];
#pragma unroll
    for (int mt = 0; mt < 2; mt++) {
        int r0 = mrow + mt * 16 + gid;
        int r1 = r0 + 8;
        aIdx[mt][0] = r0 * 4 + (tig ^ ((r0 >> 1) & 3));
        aIdx[mt][1] = r1 * 4 + (tig ^ ((r1 >> 1) & 3));
    }
#pragma unroll
    for (int nt = 0; nt < 8; nt++) {
        int nb = ncol + nt * 8 + gid;
        bIdx[nt] = nb * 4 + (tig ^ ((nb >> 1) & 3));
    }

    issue(0, 0);
    issue(1, 1);

#pragma unroll
    for (int kt = 0; kt < 16; kt++) {
        const int buf = kt % 3;
        cp_wait<1>();
        __syncthreads();

        {
            const float4* as = As4[buf];
            const float4* bs = Bs4[buf];
            unsigned au[2][2][4];
#pragma unroll
            for (int mt = 0; mt < 2; mt++) {
#pragma unroll
                for (int half = 0; half < 2; half++) {
                    float4 v = as[aIdx[mt][half]];
                    au[mt][half][0] = rna(v.x);
                    au[mt][half][1] = rna(v.y);
                    au[mt][half][2] = rna(v.z);
                    au[mt][half][3] = rna(v.w);
                }
            }
#pragma unroll
            for (int half = 0; half < 2; half++) {
                float4 b4[4];
#pragma unroll
                for (int j = 0; j < 4; j++) b4[j] = bs[bIdx[half * 4 + j]];
#pragma unroll
                for (int mt = 0; mt < 2; mt++)
#pragma unroll
                    for (int j = 0; j < 4; j++) {
                        float* cc = c[mt][half * 4 + j];
                        mma_tf32(cc,
                                 au[mt][0][0], au[mt][1][0],
                                 au[mt][0][1], au[mt][1][1],
                                 f2u(b4[j].x), f2u(b4[j].y));
                        mma_tf32(cc,
                                 au[mt][0][2], au[mt][1][2],
                                 au[mt][0][3], au[mt][1][3],
                                 f2u(b4[j].z), f2u(b4[j].w));
                    }
            }
        }
        __syncthreads();
        if (kt + 2 < 16) issue(kt + 2, (kt + 2) % 3);
    }

    // ---------------- epilogue (R12 simple scattered form) ----------------
#pragma unroll
    for (int mt = 0; mt < 2; mt++) {
#pragma unroll
        for (int nt = 0; nt < 8; nt++) {
            int clocal = ncol + nt * 8 + 2 * tig;
            int cg = c0 + clocal;
            float bias0, bias1;
            if (MODE == 1) { bias0 = b0v[cg]; bias1 = b0v[cg + 1]; }
            else if (cg < 256) { bias0 = b0v[cg]; bias1 = b0v[cg + 1]; }
            else { bias0 = b1v[cg - 256]; bias1 = b1v[cg - 255]; }
#pragma unroll
            for (int rr = 0; rr < 2; rr++) {
                int row = m0 + mrow + mt * 16 + gid + rr * 8;
                float v0 = c[mt][nt][rr * 2 + 0] + bias0;
                float v1 = c[mt][nt][rr * 2 + 1] + bias1;
                if (MODE == 1) {
                    float2* p = (float2*)(outP + (size_t)row * CDIM + cg);
                    *p = make_float2(v0, v1);
                } else {
                    int cc = cg;
                    int b = row >> 6, n = row & 63;
                    if (cc < 512) {
                        float* base;
                        if (cc < 256) { base = g_q; v0 *= SCALE; v1 *= SCALE; }
                        else { base = g_k; cc -= 256; }
                        int hh = cc >> 5, dd = cc & 31;
                        int pp = (dd & 16) + ((dd & 3) << 2) + ((dd >> 2) & 3);
                        float* p = base + ((size_t)(b * 8 + hh)) * 2048 + n * 32;
                        p[pp] = to_tf32(v0);
                        p[pp + 4] = to_tf32(v1);
                    } else {
                        cc -= 512;
                        int hh = cc >> 5, dd = cc & 31;
                        int pn = (n & ~15) + ((n & 3) << 2) + ((n >> 2) & 3);
                        float* p = g_v + ((size_t)(b * 8 + hh)) * 2048 + dd * 64 + pn;
                        p[0] = to_tf32(v0);
                        p[64] = to_tf32(v1);
                    }
                }
            }
        }
    }
}

// ---------------- tensor-core attention per (window, head) ----------------
// R12 attention + SMEM-staged fused mask+bias (the only change).
__global__ void __launch_bounds__(128) attn_kernel(const float* __restrict__ mask)
{
    __shared__ float smb[64 * 68];       // mask+bias, padded rows

    const int bh = blockIdx.x;
    const int b  = bh >> 3;
    const int h  = bh & 7;
    const int w  = b & 1023;

    const int t = threadIdx.x;
    const int wid = t >> 5, lane = t & 31;
    const int gid = lane >> 2, tig = lane & 3;
    const int i0 = wid * 16 + gid;
    const int i1 = i0 + 8;

    const float* qg = g_q + (size_t)bh * 2048;
    const float* kg = g_k + (size_t)bh * 2048;
    const float* vg = g_v + (size_t)bh * 2048;
    const float* mrow = mask + (size_t)w * 4096;
    const float* brow = g_bias8 + h * 4096;

    // ---- stage mb = mask + bias (coalesced float4 reads) ----
#pragma unroll
    for (int i = 0; i < 8; i++) {
        int u = t + i * 128;             // float4 unit 0..1023
        int row = u >> 4, cc = (u & 15) * 4;
        float4 m = *(const float4*)(mrow + u * 4);
        float4 bb = *(const float4*)(brow + u * 4);
        *(float4*)&smb[row * 68 + cc] =
            make_float4(m.x + bb.x, m.y + bb.y, m.z + bb.z, m.w + bb.w);
    }
    __syncthreads();

    // ---- Q A-fragments (direct global, permuted layout) ----
    float4 qa00 = *(const float4*)(qg + i0 * 32 + tig * 4);
    float4 qa01 = *(const float4*)(qg + i0 * 32 + 16 + tig * 4);
    float4 qa10 = *(const float4*)(qg + i1 * 32 + tig * 4);
    float4 qa11 = *(const float4*)(qg + i1 * 32 + 16 + tig * 4);

    // ---- S = Q.K^T (K direct global, as R12) ----
    float c[8][4];
#pragma unroll
    for (int nt = 0; nt < 8; nt++) {
        c[nt][0] = c[nt][1] = c[nt][2] = c[nt][3] = 0.f;
        const float* krow = kg + (8 * nt + gid) * 32;
        float4 kb0 = *(const float4*)(krow + tig * 4);
        float4 kb1 = *(const float4*)(krow + 16 + tig * 4);
        mma_tf32(c[nt], f2u(qa00.x), f2u(qa10.x), f2u(qa00.y), f2u(qa10.y), f2u(kb0.x), f2u(kb0.y));
        mma_tf32(c[nt], f2u(qa00.z), f2u(qa10.z), f2u(qa00.w), f2u(qa10.w), f2u(kb0.z), f2u(kb0.w));
        mma_tf32(c[nt], f2u(qa01.x), f2u(qa11.x), f2u(qa01.y), f2u(qa11.y), f2u(kb1.x), f2u(kb1.y));
        mma_tf32(c[nt], f2u(qa01.z), f2u(qa11.z), f2u(qa01.w), f2u(qa11.w), f2u(kb1.z), f2u(kb1.w));
    }

    // ---- add fused mask+bias from SMEM, row maxes ----
    float mx0 = -1e30f, mx1 = -1e30f;
#pragma unroll
    for (int nt = 0; nt < 8; nt++) {
        int coff = nt * 8 + 2 * tig;
        float2 m0 = *(const float2*)&smb[i0 * 68 + coff];
        float2 m1 = *(const float2*)&smb[i1 * 68 + coff];
        c[nt][0] += m0.x;
        c[nt][1] += m0.y;
        c[nt][2] += m1.x;
        c[nt][3] += m1.y;
        mx0 = fmaxf(mx0, fmaxf(c[nt][0], c[nt][1]));
        mx1 = fmaxf(mx1, fmaxf(c[nt][2], c[nt][3]));
    }
    mx0 = fmaxf(mx0, __shfl_xor_sync(~0u, mx0, 1));
    mx0 = fmaxf(mx0, __shfl_xor_sync(~0u, mx0, 2));
    mx1 = fmaxf(mx1, __shfl_xor_sync(~0u, mx1, 1));
    mx1 = fmaxf(mx1, __shfl_xor_sync(~0u, mx1, 2));

    float s0 = 0.f, s1 = 0.f;
#pragma unroll
    for (int nt = 0; nt < 8; nt++) {
        c[nt][0] = __expf(c[nt][0] - mx0);
        c[nt][1] = __expf(c[nt][1] - mx0);
        c[nt][2] = __expf(c[nt][2] - mx1);
        c[nt][3] = __expf(c[nt][3] - mx1);
        s0 += c[nt][0] + c[nt][1];
        s1 += c[nt][2] + c[nt][3];
    }
    s0 += __shfl_xor_sync(~0u, s0, 1);
    s0 += __shfl_xor_sync(~0u, s0, 2);
    s1 += __shfl_xor_sync(~0u, s1, 1);
    s1 += __shfl_xor_sync(~0u, s1, 2);
    float r0 = 1.0f / s0, r1 = 1.0f / s1;
#pragma unroll
    for (int nt = 0; nt < 8; nt++) {
        c[nt][0] = to_tf32(c[nt][0] * r0);
        c[nt][1] = to_tf32(c[nt][1] * r0);
        c[nt][2] = to_tf32(c[nt][2] * r1);
        c[nt][3] = to_tf32(c[nt][3] * r1);
    }

    // ---- P C-layout -> A-fragments via shuffles ----
    unsigned a[8][4];
    const int src1 = (gid << 2) + (tig >> 1);
    const int src2 = src1 + 2;
    const bool odd = (tig & 1);
#pragma unroll
    for (int kt = 0; kt < 8; kt++) {
        float p0 = __shfl_sync(~0u, c[kt][0], src1);
        float p1 = __shfl_sync(~0u, c[kt][1], src1);
        float p2 = __shfl_sync(~0u, c[kt][2], src1);
        float p3 = __shfl_sync(~0u, c[kt][3], src1);
        float q0 = __shfl_sync(~0u, c[kt][0], src2);
        float q1 = __shfl_sync(~0u, c[kt][1], src2);
        float q2 = __shfl_sync(~0u, c[kt][2], src2);
        float q3 = __shfl_sync(~0u, c[kt][3], src2);
        a[kt][0] = f2u(odd ? p1 : p0);
        a[kt][1] = f2u(odd ? p3 : p2);
        a[kt][2] = f2u(odd ? q1 : q0);
        a[kt][3] = f2u(odd ? q3 : q2);
    }

    // ---- O = P.V (V direct global, as R12) ----
    float co[4][4];
#pragma unroll
    for (int nt = 0; nt < 4; nt++)
        co[nt][0] = co[nt][1] = co[nt][2] = co[nt][3] = 0.f;

#pragma unroll
    for (int g = 0; g < 4; g++) {
        float4 vb[4];
#pragma unroll
        for (int nt = 0; nt < 4; nt++)
            vb[nt] = *(const float4*)(vg + (8 * nt + gid) * 64 + g * 16 + tig * 4);
        int kt0 = 2 * g;
#pragma unroll
        for (int nt = 0; nt < 4; nt++) {
            mma_tf32(co[nt], a[kt0][0], a[kt0][1], a[kt0][2], a[kt0][3],
                     f2u(vb[nt].x), f2u(vb[nt].y));
            mma_tf32(co[nt], a[kt0 + 1][0], a[kt0 + 1][1], a[kt0 + 1][2], a[kt0 + 1][3],
                     f2u(vb[nt].z), f2u(vb[nt].w));
        }
    }

    // store O tf32-rounded: g_o[m][h*32 + d]
    size_t orow0 = ((size_t)(b * 64 + i0)) * CDIM + h * 32;
    size_t orow1 = ((size_t)(b * 64 + i1)) * CDIM + h * 32;
#pragma unroll
    for (int nt = 0; nt < 4; nt++) {
        int col = nt * 8 + 2 * tig;
        *(float2*)&g_o[orow0 + col] = make_float2(to_tf32(co[nt][0]), to_tf32(co[nt][1]));
        *(float2*)&g_o[orow1 + col] = make_float2(to_tf32(co[nt][2]), to_tf32(co[nt][3]));
    }
}

// ---------------- launch ----------------
extern "C" void kernel_launch(void* const* d_in, const int* in_sizes, int n_in,
                              void* d_out, int out_size)
{
    const float* x          = (const float*)d_in[0];
    const float* mask       = (const float*)d_in[1];
    const float* Wq         = (const float*)d_in[2];
    const float* bq         = (const float*)d_in[3];
    const float* Wkv        = (const float*)d_in[4];
    const float* bkv        = (const float*)d_in[5];
    const float* bias_table = (const float*)d_in[6];
    const float* Wp         = (const float*)d_in[7];
    const float* bp         = (const float*)d_in[8];
    float* out = (float*)d_out;

    round_w<<<256, 256>>>(Wq, Wkv, Wp);
    bias8_kernel<<<128, 256>>>(bias_table);
    mma_gemm<0><<<dim3(6, MROWS / 128), 256>>>(x, bq, bkv, nullptr);
    attn_kernel<<<BWIN * HEADS, 128>>>(mask);
    mma_gemm<1><<<dim3(2, MROWS / 128), 256>>>(nullptr, bp, nullptr, out);
}

// round 16
// speedup vs baseline: 1.2284x; 1.2013x over previous
#include <cuda_runtime.h>
#include <cuda_fp16.h>
#include <cstddef>
#include <cstdint>
#include <cstring>

// ---------------- problem constants ----------------
constexpr int BWIN = 4096;
constexpr int NTOK = 64;
constexpr int CDIM = 256;
constexpr int HEADS = 8;
constexpr int MROWS = BWIN * NTOK;          // 262144
constexpr float SCALE = 0.1767766952966369f; // 32^-0.5

// ---------------- scratch ----------------
// q/k: fp16 [bh][n][32] plain.  v: fp16 [bh][d][64] plain (transposed).
__device__ __half g_q[BWIN * HEADS * NTOK * 32];
__device__ __half g_k[BWIN * HEADS * NTOK * 32];
__device__ __half g_v[BWIN * HEADS * NTOK * 32];
__device__ float g_o[MROWS * CDIM];         // tf32-rounded fp32 [m][256]
__device__ float g_wt[1024 * CDIM];         // RNA-rounded weights
__device__ float g_bias8[HEADS * 64 * 64];

// ---------------- helpers ----------------
__device__ __forceinline__ float to_tf32(float x) {
    unsigned r;
    asm("cvt.rna.tf32.f32 %0, %1;" : "=r"(r) : "f"(x));
    return __uint_as_float(r);
}
__device__ __forceinline__ unsigned f2u(float x) { return __float_as_uint(x); }
__device__ __forceinline__ unsigned rna(float x) { return __float_as_uint(x) + 0x1000u; }
__device__ __forceinline__ unsigned pack_h2(float lo, float hi) {
    __half2 h = __floats2half2_rn(lo, hi);
    unsigned u;
    memcpy(&u, &h, 4);
    return u;
}

__device__ __forceinline__ void mma_tf32(float* c, unsigned a0, unsigned a1,
                                         unsigned a2, unsigned a3,
                                         unsigned b0, unsigned b1) {
    asm volatile(
        "mma.sync.aligned.m16n8k8.row.col.f32.tf32.tf32.f32 "
        "{%0,%1,%2,%3}, {%4,%5,%6,%7}, {%8,%9}, {%0,%1,%2,%3};"
        : "+f"(c[0]), "+f"(c[1]), "+f"(c[2]), "+f"(c[3])
        : "r"(a0), "r"(a1), "r"(a2), "r"(a3), "r"(b0), "r"(b1));
}

__device__ __forceinline__ void mma_f16(float* c, unsigned a0, unsigned a1,
                                        unsigned a2, unsigned a3,
                                        unsigned b0, unsigned b1) {
    asm volatile(
        "mma.sync.aligned.m16n8k16.row.col.f32.f16.f16.f32 "
        "{%0,%1,%2,%3}, {%4,%5,%6,%7}, {%8,%9}, {%0,%1,%2,%3};"
        : "+f"(c[0]), "+f"(c[1]), "+f"(c[2]), "+f"(c[3])
        : "r"(a0), "r"(a1), "r"(a2), "r"(a3), "r"(b0), "r"(b1));
}

__device__ __forceinline__ void cp16(uint32_t dst, const void* src) {
    asm volatile("cp.async.cg.shared.global [%0], [%1], 16;" :: "r"(dst), "l"(src) : "memory");
}
__device__ __forceinline__ void cp_commit() {
    asm volatile("cp.async.commit_group;" ::: "memory");
}
template <int N>
__device__ __forceinline__ void cp_wait() {
    asm volatile("cp.async.wait_group %0;" :: "n"(N) : "memory");
}

// ---------------- round weights (RNA tf32) into g_wt ----------------
__global__ void __launch_bounds__(256) round_w(
    const float* __restrict__ Wq, const float* __restrict__ Wkv,
    const float* __restrict__ Wp)
{
    int fi = blockIdx.x * 256 + threadIdx.x;
    int row = fi >> 6;
    int col4 = fi & 63;
    const float* src;
    if (row < 256) src = Wq + ((size_t)row * 64 + col4) * 4;
    else if (row < 768) src = Wkv + ((size_t)(row - 256) * 64 + col4) * 4;
    else src = Wp + ((size_t)(row - 768) * 64 + col4) * 4;
    float4 v = *(const float4*)src;
    *((float4*)g_wt + fi) =
        make_float4(to_tf32(v.x), to_tf32(v.y), to_tf32(v.z), to_tf32(v.w));
}

// ---------------- expand relative-position bias to [h][i][j] ----------------
__global__ void __launch_bounds__(256) bias8_kernel(const float* __restrict__ bias_table)
{
    int idx = blockIdx.x * 256 + threadIdx.x;
    int h = idx >> 12;
    int ij = idx & 4095;
    int i = ij >> 6, j = ij & 63;
    int ih = i >> 3, iw = i & 7, jh = j >> 3, jw = j & 7;
    int ridx = (ih - jh + 7) * 15 + (iw - jw + 7);
    g_bias8[idx] = bias_table[ridx * 8 + h];
}

// ---------------- TF32 tensor GEMM, cp.async 3-stage ----------------
// MODE 0: A=x; scatter -> fp16 g_q/g_k/g_v (plain layouts). MODE 1: A=g_o -> outP.
template <int MODE>
__global__ void __launch_bounds__(256, 2) mma_gemm(
    const float* __restrict__ A_in,
    const float* __restrict__ b0v, const float* __restrict__ b1v,
    float* __restrict__ outP)
{
    constexpr int STAGES = 3;
    __shared__ float4 As4[STAGES][128 * 4];
    __shared__ float4 Bs4[STAGES][128 * 4];

    const float* A = (MODE == 0) ? A_in : g_o;
    const int c0 = blockIdx.x * 128;
    const int m0 = blockIdx.y * 128;
    const float* Wsrc = g_wt + (size_t)((MODE == 0 ? 0 : 768) + c0) * CDIM;

    const int t = threadIdx.x;
    const int wid = t >> 5, lane = t & 31;
    const int wm = wid & 3, wn = wid >> 2;
    const int gid = lane >> 2, tig = lane & 3;
    const int mrow = wm * 32, ncol = wn * 64;

    float c[2][8][4];
#pragma unroll
    for (int mt = 0; mt < 2; mt++)
#pragma unroll
        for (int nt = 0; nt < 8; nt++)
#pragma unroll
            for (int i = 0; i < 4; i++) c[mt][nt][i] = 0.f;

    const int arow = t >> 2;
    const int ac = t & 3;
    const int apc  = ac ^ ((arow >> 1) & 3);
    const int arowB = arow + 64;
    const int apcB = ac ^ ((arowB >> 1) & 3);

    const uint32_t dA0 = (uint32_t)__cvta_generic_to_shared(&As4[0][arow * 4 + apc]);
    const uint32_t dA1 = (uint32_t)__cvta_generic_to_shared(&As4[0][arowB * 4 + apcB]);
    const uint32_t dB0 = (uint32_t)__cvta_generic_to_shared(&Bs4[0][arow * 4 + apc]);
    const uint32_t dB1 = (uint32_t)__cvta_generic_to_shared(&Bs4[0][arowB * 4 + apcB]);
    constexpr uint32_t STRIDE = 128 * 4 * 16;

    const float* srcA0 = A + (size_t)(m0 + arow) * CDIM + ac * 4;
    const float* srcA1 = A + (size_t)(m0 + arow + 64) * CDIM + ac * 4;
    const float* srcB0 = Wsrc + (size_t)arow * CDIM + ac * 4;
    const float* srcB1 = Wsrc + (size_t)(arow + 64) * CDIM + ac * 4;

    auto issue = [&](int kt, int s) {
        cp16(dA0 + s * STRIDE, srcA0 + kt * 16);
        cp16(dA1 + s * STRIDE, srcA1 + kt * 16);
        cp16(dB0 + s * STRIDE, srcB0 + kt * 16);
        cp16(dB1 + s * STRIDE, srcB1 + kt * 16);
        cp_commit();
    };

    int aIdx[2][2], bIdx[8];
#pragma unroll
    for (int mt = 0; mt < 2; mt++) {
        int r0 = mrow + mt * 16 + gid;
        int r1 = r0 + 8;
        aIdx[mt][0] = r0 * 4 + (tig ^ ((r0 >> 1) & 3));
        aIdx[mt][1] = r1 * 4 + (tig ^ ((r1 >> 1) & 3));
    }
#pragma unroll
    for (int nt = 0; nt < 8; nt++) {
        int nb = ncol + nt * 8 + gid;
        bIdx[nt] = nb * 4 + (tig ^ ((nb >> 1) & 3));
    }

    issue(0, 0);
    issue(1, 1);

#pragma unroll
    for (int kt = 0; kt < 16; kt++) {
        const int buf = kt % 3;
        cp_wait<1>();
        __syncthreads();

        {
            const float4* as = As4[buf];
            const float4* bs = Bs4[buf];
            unsigned au[2][2][4];
#pragma unroll
            for (int mt = 0; mt < 2; mt++) {
#pragma unroll
                for (int half = 0; half < 2; half++) {
                    float4 v = as[aIdx[mt][half]];
                    au[mt][half][0] = rna(v.x);
                    au[mt][half][1] = rna(v.y);
                    au[mt][half][2] = rna(v.z);
                    au[mt][half][3] = rna(v.w);
                }
            }
#pragma unroll
            for (int half = 0; half < 2; half++) {
                float4 b4[4];
#pragma unroll
                for (int j = 0; j < 4; j++) b4[j] = bs[bIdx[half * 4 + j]];
#pragma unroll
                for (int mt = 0; mt < 2; mt++)
#pragma unroll
                    for (int j = 0; j < 4; j++) {
                        float* cc = c[mt][half * 4 + j];
                        mma_tf32(cc,
                                 au[mt][0][0], au[mt][1][0],
                                 au[mt][0][1], au[mt][1][1],
                                 f2u(b4[j].x), f2u(b4[j].y));
                        mma_tf32(cc,
                                 au[mt][0][2], au[mt][1][2],
                                 au[mt][0][3], au[mt][1][3],
                                 f2u(b4[j].z), f2u(b4[j].w));
                    }
            }
        }
        __syncthreads();
        if (kt + 2 < 16) issue(kt + 2, (kt + 2) % 3);
    }

    // ---------------- epilogue ----------------
#pragma unroll
    for (int mt = 0; mt < 2; mt++) {
#pragma unroll
        for (int nt = 0; nt < 8; nt++) {
            int clocal = ncol + nt * 8 + 2 * tig;
            int cg = c0 + clocal;
            float bias0, bias1;
            if (MODE == 1) { bias0 = b0v[cg]; bias1 = b0v[cg + 1]; }
            else if (cg < 256) { bias0 = b0v[cg]; bias1 = b0v[cg + 1]; }
            else { bias0 = b1v[cg - 256]; bias1 = b1v[cg - 255]; }
#pragma unroll
            for (int rr = 0; rr < 2; rr++) {
                int row = m0 + mrow + mt * 16 + gid + rr * 8;
                float v0 = c[mt][nt][rr * 2 + 0] + bias0;
                float v1 = c[mt][nt][rr * 2 + 1] + bias1;
                if (MODE == 1) {
                    float2* p = (float2*)(outP + (size_t)row * CDIM + cg);
                    *p = make_float2(v0, v1);
                } else {
                    int cc = cg;
                    int b = row >> 6, n = row & 63;
                    if (cc < 512) {
                        __half* base;
                        float scl = 1.0f;
                        if (cc < 256) { base = g_q; scl = SCALE; }
                        else { base = g_k; cc -= 256; }
                        int hh = cc >> 5, dd = cc & 31;    // dd even
                        *(__half2*)(base + ((size_t)(b * 8 + hh)) * 2048 + n * 32 + dd) =
                            __floats2half2_rn(v0 * scl, v1 * scl);
                    } else {
                        cc -= 512;
                        int hh = cc >> 5, dd = cc & 31;
                        __half* p = g_v + ((size_t)(b * 8 + hh)) * 2048 + dd * 64 + n;
                        p[0] = __float2half_rn(v0);
                        p[64] = __float2half_rn(v1);
                    }
                }
            }
        }
    }
}

// ---------------- fp16 tensor-core attention per (window, head) ----------------
__global__ void __launch_bounds__(128) attn_kernel(const float* __restrict__ mask)
{
    __shared__ float smb[64 * 68];       // mask+bias, padded rows

    const int bh = blockIdx.x;
    const int b  = bh >> 3;
    const int h  = bh & 7;
    const int w  = b & 1023;

    const int t = threadIdx.x;
    const int wid = t >> 5, lane = t & 31;
    const int gid = lane >> 2, tig = lane & 3;
    const int i0 = wid * 16 + gid;
    const int i1 = i0 + 8;

    const __half* qg = g_q + (size_t)bh * 2048;
    const __half* kg = g_k + (size_t)bh * 2048;
    const __half* vg = g_v + (size_t)bh * 2048;
    const float* mrow = mask + (size_t)w * 4096;
    const float* brow = g_bias8 + h * 4096;

    // ---- stage mb = mask + bias ----
#pragma unroll
    for (int i = 0; i < 8; i++) {
        int u = t + i * 128;
        int row = u >> 4, cc = (u & 15) * 4;
        float4 m = *(const float4*)(mrow + u * 4);
        float4 bb = *(const float4*)(brow + u * 4);
        *(float4*)&smb[row * 68 + cc] =
            make_float4(m.x + bb.x, m.y + bb.y, m.z + bb.z, m.w + bb.w);
    }
    __syncthreads();

    // ---- Q fragments: one uint4 per row = halves [8tig..8tig+7] ----
    uint4 qi0 = *(const uint4*)(qg + i0 * 32 + 8 * tig);
    uint4 qi1 = *(const uint4*)(qg + i1 * 32 + 8 * tig);

    // ---- S = Q.K^T : 8 n-tiles x 2 m16n8k16 ----
    float c[8][4];
#pragma unroll
    for (int nt = 0; nt < 8; nt++) {
        c[nt][0] = c[nt][1] = c[nt][2] = c[nt][3] = 0.f;
        uint4 kv = *(const uint4*)(kg + (8 * nt + gid) * 32 + 8 * tig);
        mma_f16(c[nt], qi0.x, qi1.x, qi0.y, qi1.y, kv.x, kv.y);
        mma_f16(c[nt], qi0.z, qi1.z, qi0.w, qi1.w, kv.z, kv.w);
    }

    // ---- add fused mask+bias from SMEM, row maxes ----
    float mx0 = -1e30f, mx1 = -1e30f;
#pragma unroll
    for (int nt = 0; nt < 8; nt++) {
        int coff = nt * 8 + 2 * tig;
        float2 m0 = *(const float2*)&smb[i0 * 68 + coff];
        float2 m1 = *(const float2*)&smb[i1 * 68 + coff];
        c[nt][0] += m0.x;
        c[nt][1] += m0.y;
        c[nt][2] += m1.x;
        c[nt][3] += m1.y;
        mx0 = fmaxf(mx0, fmaxf(c[nt][0], c[nt][1]));
        mx1 = fmaxf(mx1, fmaxf(c[nt][2], c[nt][3]));
    }
    mx0 = fmaxf(mx0, __shfl_xor_sync(~0u, mx0, 1));
    mx0 = fmaxf(mx0, __shfl_xor_sync(~0u, mx0, 2));
    mx1 = fmaxf(mx1, __shfl_xor_sync(~0u, mx1, 1));
    mx1 = fmaxf(mx1, __shfl_xor_sync(~0u, mx1, 2));

    float s0 = 0.f, s1 = 0.f;
#pragma unroll
    for (int nt = 0; nt < 8; nt++) {
        c[nt][0] = __expf(c[nt][0] - mx0);
        c[nt][1] = __expf(c[nt][1] - mx0);
        c[nt][2] = __expf(c[nt][2] - mx1);
        c[nt][3] = __expf(c[nt][3] - mx1);
        s0 += c[nt][0] + c[nt][1];
        s1 += c[nt][2] + c[nt][3];
    }
    s0 += __shfl_xor_sync(~0u, s0, 1);
    s0 += __shfl_xor_sync(~0u, s0, 2);
    s1 += __shfl_xor_sync(~0u, s1, 1);
    s1 += __shfl_xor_sync(~0u, s1, 2);
    float r0 = 1.0f / s0, r1 = 1.0f / s1;

    // ---- pack P rows into half2 (lo = even col) ----
    unsigned h01[8], h23[8];
#pragma unroll
    for (int nt = 0; nt < 8; nt++) {
        h01[nt] = pack_h2(c[nt][0] * r0, c[nt][1] * r0);   // row i0, j (8nt+2tig, +1)
        h23[nt] = pack_h2(c[nt][2] * r1, c[nt][3] * r1);   // row i1
    }

    // ---- O = P.V : 4 d-tiles x 4 j-groups of m16n8k16 ----
    const int sA = (gid << 2) + 2 * (tig & 1);
    const int sB = sA + 1;
    const bool hi = (tig & 2) != 0;

    float co[4][4];
#pragma unroll
    for (int dt = 0; dt < 4; dt++)
        co[dt][0] = co[dt][1] = co[dt][2] = co[dt][3] = 0.f;

#pragma unroll
    for (int g = 0; g < 4; g++) {
        unsigned uA0 = __shfl_sync(~0u, h01[2 * g],     sA);
        unsigned uA1 = __shfl_sync(~0u, h01[2 * g + 1], sA);
        unsigned uB0 = __shfl_sync(~0u, h01[2 * g],     sB);
        unsigned uB1 = __shfl_sync(~0u, h01[2 * g + 1], sB);
        unsigned vA0 = __shfl_sync(~0u, h23[2 * g],     sA);
        unsigned vA1 = __shfl_sync(~0u, h23[2 * g + 1], sA);
        unsigned vB0 = __shfl_sync(~0u, h23[2 * g],     sB);
        unsigned vB1 = __shfl_sync(~0u, h23[2 * g + 1], sB);
        unsigned a0 = hi ? uA1 : uA0;     // P[i0][16g+4tig, +1]
        unsigned a1 = hi ? vA1 : vA0;     // P[i1][16g+4tig, +1]
        unsigned a2 = hi ? uB1 : uB0;     // P[i0][16g+4tig+2, +3]
        unsigned a3 = hi ? vB1 : vB0;     // P[i1][16g+4tig+2, +3]
#pragma unroll
        for (int dt = 0; dt < 4; dt++) {
            uint2 vv = *(const uint2*)(vg + (8 * dt + gid) * 64 + 16 * g + 4 * tig);
            mma_f16(co[dt], a0, a1, a2, a3, vv.x, vv.y);
        }
    }

    // ---- store O tf32-rounded fp32: g_o[m][h*32 + d] ----
    size_t orow0 = ((size_t)(b * 64 + i0)) * CDIM + h * 32;
    size_t orow1 = ((size_t)(b * 64 + i1)) * CDIM + h * 32;
#pragma unroll
    for (int dt = 0; dt < 4; dt++) {
        int col = dt * 8 + 2 * tig;
        *(float2*)&g_o[orow0 + col] = make_float2(to_tf32(co[dt][0]), to_tf32(co[dt][1]));
        *(float2*)&g_o[orow1 + col] = make_float2(to_tf32(co[dt][2]), to_tf32(co[dt][3]));
    }
}

// ---------------- launch ----------------
extern "C" void kernel_launch(void* const* d_in, const int* in_sizes, int n_in,
                              void* d_out, int out_size)
{
    const float* x          = (const float*)d_in[0];
    const float* mask       = (const float*)d_in[1];
    const float* Wq         = (const float*)d_in[2];
    const float* bq         = (const float*)d_in[3];
    const float* Wkv        = (const float*)d_in[4];
    const float* bkv        = (const float*)d_in[5];
    const float* bias_table = (const float*)d_in[6];
    const float* Wp         = (const float*)d_in[7];
    const float* bp         = (const float*)d_in[8];
    float* out = (float*)d_out;

    round_w<<<256, 256>>>(Wq, Wkv, Wp);
    bias8_kernel<<<128, 256>>>(bias_table);
    mma_gemm<0><<<dim3(6, MROWS / 128), 256>>>(x, bq, bkv, nullptr);
    attn_kernel<<<BWIN * HEADS, 128>>>(mask);
    mma_gemm<1><<<dim3(2, MROWS / 128), 256>>>(nullptr, bp, nullptr, out);
}

// round 17
// speedup vs baseline: 1.4707x; 1.1973x over previous
#include <cuda_runtime.h>
#include <cuda_fp16.h>
#include <cstddef>
#include <cstdint>
#include <cstring>

// ---------------- problem constants ----------------
constexpr int BWIN = 4096;
constexpr int NTOK = 64;
constexpr int CDIM = 256;
constexpr int HEADS = 8;
constexpr int MROWS = BWIN * NTOK;          // 262144
constexpr float SCALE = 0.1767766952966369f; // 32^-0.5

// ---------------- scratch ----------------
__device__ __half g_q[BWIN * HEADS * NTOK * 32];    // [bh][n][32]
__device__ __half g_k[BWIN * HEADS * NTOK * 32];    // [bh][n][32]
__device__ __half g_v[BWIN * HEADS * NTOK * 32];    // [bh][d][64] transposed
__device__ __half g_oh[MROWS * CDIM];               // attention output, fp16 [m][256]
__device__ __half g_xh[MROWS * CDIM];               // x in fp16
__device__ __half g_wh[1024 * CDIM];                // weights fp16: Wq, Wkv, Wp
__device__ float g_bias8[HEADS * 64 * 64];

// ---------------- helpers ----------------
__device__ __forceinline__ float to_tf32(float x) {
    unsigned r;
    asm("cvt.rna.tf32.f32 %0, %1;" : "=r"(r) : "f"(x));
    return __uint_as_float(r);
}
__device__ __forceinline__ unsigned pack_h2(float lo, float hi) {
    __half2 h = __floats2half2_rn(lo, hi);
    unsigned u;
    memcpy(&u, &h, 4);
    return u;
}

__device__ __forceinline__ void mma_f16(float* c, unsigned a0, unsigned a1,
                                        unsigned a2, unsigned a3,
                                        unsigned b0, unsigned b1) {
    asm volatile(
        "mma.sync.aligned.m16n8k16.row.col.f32.f16.f16.f32 "
        "{%0,%1,%2,%3}, {%4,%5,%6,%7}, {%8,%9}, {%0,%1,%2,%3};"
        : "+f"(c[0]), "+f"(c[1]), "+f"(c[2]), "+f"(c[3])
        : "r"(a0), "r"(a1), "r"(a2), "r"(a3), "r"(b0), "r"(b1));
}

__device__ __forceinline__ void cp16(uint32_t dst, const void* src) {
    asm volatile("cp.async.cg.shared.global [%0], [%1], 16;" :: "r"(dst), "l"(src) : "memory");
}
__device__ __forceinline__ void cp_commit() {
    asm volatile("cp.async.commit_group;" ::: "memory");
}
template <int N>
__device__ __forceinline__ void cp_wait() {
    asm volatile("cp.async.wait_group %0;" :: "n"(N) : "memory");
}

// ---------------- convert x to fp16 ----------------
__global__ void __launch_bounds__(256) conv_x(const float* __restrict__ x)
{
    size_t i = (size_t)blockIdx.x * 256 + threadIdx.x;   // float4 unit
    float4 v = ((const float4*)x)[i];
    __half2 h0 = __floats2half2_rn(v.x, v.y);
    __half2 h1 = __floats2half2_rn(v.z, v.w);
    unsigned u0, u1;
    memcpy(&u0, &h0, 4);
    memcpy(&u1, &h1, 4);
    ((uint2*)g_xh)[i] = make_uint2(u0, u1);
}

// ---------------- convert weights to fp16 into g_wh ----------------
__global__ void __launch_bounds__(256) round_w(
    const float* __restrict__ Wq, const float* __restrict__ Wkv,
    const float* __restrict__ Wp)
{
    int fi = blockIdx.x * 256 + threadIdx.x;    // float4 index, 0..65535
    int row = fi >> 6;
    int col4 = fi & 63;
    const float* src;
    if (row < 256) src = Wq + ((size_t)row * 64 + col4) * 4;
    else if (row < 768) src = Wkv + ((size_t)(row - 256) * 64 + col4) * 4;
    else src = Wp + ((size_t)(row - 768) * 64 + col4) * 4;
    float4 v = *(const float4*)src;
    __half2 h0 = __floats2half2_rn(v.x, v.y);
    __half2 h1 = __floats2half2_rn(v.z, v.w);
    unsigned u0, u1;
    memcpy(&u0, &h0, 4);
    memcpy(&u1, &h1, 4);
    ((uint2*)g_wh)[fi] = make_uint2(u0, u1);
}

// ---------------- expand relative-position bias to [h][i][j] ----------------
__global__ void __launch_bounds__(256) bias8_kernel(const float* __restrict__ bias_table)
{
    int idx = blockIdx.x * 256 + threadIdx.x;
    int h = idx >> 12;
    int ij = idx & 4095;
    int i = ij >> 6, j = ij & 63;
    int ih = i >> 3, iw = i & 7, jh = j >> 3, jw = j & 7;
    int ridx = (ih - jh + 7) * 15 + (iw - jw + 7);
    g_bias8[idx] = bias_table[ridx * 8 + h];
}

// ---------------- FP16 tensor GEMM, cp.async 3-stage ----------------
// CTA tile 128x128xK256 (8 chunks of k32); 8 warps (4m x 2n), warp tile 32x64.
// SMEM row = 64B (32 halves) = 4 chunks of 16B, XOR swizzle ^((row>>1)&3).
// MODE 0: A=g_xh; W rows c0.. of g_wh; scatter -> g_q/g_k/g_v (fp16).
// MODE 1: A=g_oh; W rows 768+c0.. -> outP (fp32).
template <int MODE>
__global__ void __launch_bounds__(256, 2) mma_gemm(
    const float* __restrict__ b0v, const float* __restrict__ b1v,
    float* __restrict__ outP)
{
    constexpr int STAGES = 3;
    __shared__ uint4 As4[STAGES][128 * 4];
    __shared__ uint4 Bs4[STAGES][128 * 4];

    const __half* A = (MODE == 0) ? g_xh : g_oh;
    const int c0 = blockIdx.x * 128;
    const int m0 = blockIdx.y * 128;
    const __half* Wsrc = g_wh + (size_t)((MODE == 0 ? 0 : 768) + c0) * CDIM;

    const int t = threadIdx.x;
    const int wid = t >> 5, lane = t & 31;
    const int wm = wid & 3, wn = wid >> 2;
    const int gid = lane >> 2, tig = lane & 3;
    const int mrow = wm * 32, ncol = wn * 64;

    float c[2][8][4];
#pragma unroll
    for (int mt = 0; mt < 2; mt++)
#pragma unroll
        for (int nt = 0; nt < 8; nt++)
#pragma unroll
            for (int i = 0; i < 4; i++) c[mt][nt][i] = 0.f;

    // ---- cp.async mapping: rows t>>2 and t>>2+64, chunk t&3 (16B = 8 halves) ----
    const int arow = t >> 2;
    const int ac = t & 3;
    const int apc  = ac ^ ((arow >> 1) & 3);
    const int arowB = arow + 64;
    const int apcB = ac ^ ((arowB >> 1) & 3);

    const uint32_t dA0 = (uint32_t)__cvta_generic_to_shared(&As4[0][arow * 4 + apc]);
    const uint32_t dA1 = (uint32_t)__cvta_generic_to_shared(&As4[0][arowB * 4 + apcB]);
    const uint32_t dB0 = (uint32_t)__cvta_generic_to_shared(&Bs4[0][arow * 4 + apc]);
    const uint32_t dB1 = (uint32_t)__cvta_generic_to_shared(&Bs4[0][arowB * 4 + apcB]);
    constexpr uint32_t STRIDE = 128 * 4 * 16;   // 8 KB per stage

    const __half* srcA0 = A + (size_t)(m0 + arow) * CDIM + ac * 8;
    const __half* srcA1 = A + (size_t)(m0 + arow + 64) * CDIM + ac * 8;
    const __half* srcB0 = Wsrc + (size_t)arow * CDIM + ac * 8;
    const __half* srcB1 = Wsrc + (size_t)(arow + 64) * CDIM + ac * 8;

    auto issue = [&](int kt, int s) {      // kt = k32 chunk index 0..7
        cp16(dA0 + s * STRIDE, srcA0 + kt * 32);
        cp16(dA1 + s * STRIDE, srcA1 + kt * 32);
        cp16(dB0 + s * STRIDE, srcB0 + kt * 32);
        cp16(dB1 + s * STRIDE, srcB1 + kt * 32);
        cp_commit();
    };

    // ---- fragment load indices (uint4 units) ----
    int aIdx[2][2], bIdx[8];
#pragma unroll
    for (int mt = 0; mt < 2; mt++) {
        int r0 = mrow + mt * 16 + gid;
        int r1 = r0 + 8;
        aIdx[mt][0] = r0 * 4 + (tig ^ ((r0 >> 1) & 3));
        aIdx[mt][1] = r1 * 4 + (tig ^ ((r1 >> 1) & 3));
    }
#pragma unroll
    for (int nt = 0; nt < 8; nt++) {
        int nb = ncol + nt * 8 + gid;
        bIdx[nt] = nb * 4 + (tig ^ ((nb >> 1) & 3));
    }

    issue(0, 0);
    issue(1, 1);

#pragma unroll
    for (int kt = 0; kt < 8; kt++) {
        const int buf = kt % 3;
        cp_wait<1>();
        __syncthreads();

        {
            const uint4* as = As4[buf];
            const uint4* bs = Bs4[buf];
            uint4 a4[2][2];
#pragma unroll
            for (int mt = 0; mt < 2; mt++) {
                a4[mt][0] = as[aIdx[mt][0]];   // row r0: halves 8tig..8tig+7
                a4[mt][1] = as[aIdx[mt][1]];   // row r1
            }
#pragma unroll
            for (int half = 0; half < 2; half++) {
                uint4 b4[4];
#pragma unroll
                for (int j = 0; j < 4; j++) b4[j] = bs[bIdx[half * 4 + j]];
#pragma unroll
                for (int mt = 0; mt < 2; mt++)
#pragma unroll
                    for (int j = 0; j < 4; j++) {
                        float* cc = c[mt][half * 4 + j];
                        // MMA0: k-pairs P0,P1 ; MMA1: k-pairs P2,P3
                        mma_f16(cc, a4[mt][0].x, a4[mt][1].x,
                                    a4[mt][0].y, a4[mt][1].y,
                                    b4[j].x,     b4[j].y);
                        mma_f16(cc, a4[mt][0].z, a4[mt][1].z,
                                    a4[mt][0].w, a4[mt][1].w,
                                    b4[j].z,     b4[j].w);
                    }
            }
        }
        __syncthreads();
        if (kt + 2 < 8) issue(kt + 2, (kt + 2) % 3);
    }

    // ---------------- epilogue ----------------
#pragma unroll
    for (int mt = 0; mt < 2; mt++) {
#pragma unroll
        for (int nt = 0; nt < 8; nt++) {
            int clocal = ncol + nt * 8 + 2 * tig;
            int cg = c0 + clocal;
            float bias0, bias1;
            if (MODE == 1) { bias0 = b0v[cg]; bias1 = b0v[cg + 1]; }
            else if (cg < 256) { bias0 = b0v[cg]; bias1 = b0v[cg + 1]; }
            else { bias0 = b1v[cg - 256]; bias1 = b1v[cg - 255]; }
#pragma unroll
            for (int rr = 0; rr < 2; rr++) {
                int row = m0 + mrow + mt * 16 + gid + rr * 8;
                float v0 = c[mt][nt][rr * 2 + 0] + bias0;
                float v1 = c[mt][nt][rr * 2 + 1] + bias1;
                if (MODE == 1) {
                    float2* p = (float2*)(outP + (size_t)row * CDIM + cg);
                    *p = make_float2(v0, v1);
                } else {
                    int cc = cg;
                    int b = row >> 6, n = row & 63;
                    if (cc < 512) {
                        __half* base;
                        float scl = 1.0f;
                        if (cc < 256) { base = g_q; scl = SCALE; }
                        else { base = g_k; cc -= 256; }
                        int hh = cc >> 5, dd = cc & 31;    // dd even
                        *(__half2*)(base + ((size_t)(b * 8 + hh)) * 2048 + n * 32 + dd) =
                            __floats2half2_rn(v0 * scl, v1 * scl);
                    } else {
                        cc -= 512;
                        int hh = cc >> 5, dd = cc & 31;
                        __half* p = g_v + ((size_t)(b * 8 + hh)) * 2048 + dd * 64 + n;
                        p[0] = __float2half_rn(v0);
                        p[64] = __float2half_rn(v1);
                    }
                }
            }
        }
    }
}

// ---------------- fp16 tensor-core attention per (window, head) ----------------
__global__ void __launch_bounds__(128) attn_kernel(const float* __restrict__ mask)
{
    __shared__ float smb[64 * 68];       // mask+bias, padded rows

    const int bh = blockIdx.x;
    const int b  = bh >> 3;
    const int h  = bh & 7;
    const int w  = b & 1023;

    const int t = threadIdx.x;
    const int wid = t >> 5, lane = t & 31;
    const int gid = lane >> 2, tig = lane & 3;
    const int i0 = wid * 16 + gid;
    const int i1 = i0 + 8;

    const __half* qg = g_q + (size_t)bh * 2048;
    const __half* kg = g_k + (size_t)bh * 2048;
    const __half* vg = g_v + (size_t)bh * 2048;
    const float* mrow = mask + (size_t)w * 4096;
    const float* brow = g_bias8 + h * 4096;

    // ---- stage mb = mask + bias ----
#pragma unroll
    for (int i = 0; i < 8; i++) {
        int u = t + i * 128;
        int row = u >> 4, cc = (u & 15) * 4;
        float4 m = *(const float4*)(mrow + u * 4);
        float4 bb = *(const float4*)(brow + u * 4);
        *(float4*)&smb[row * 68 + cc] =
            make_float4(m.x + bb.x, m.y + bb.y, m.z + bb.z, m.w + bb.w);
    }
    __syncthreads();

    // ---- Q fragments ----
    uint4 qi0 = *(const uint4*)(qg + i0 * 32 + 8 * tig);
    uint4 qi1 = *(const uint4*)(qg + i1 * 32 + 8 * tig);

    // ---- S = Q.K^T ----
    float c[8][4];
#pragma unroll
    for (int nt = 0; nt < 8; nt++) {
        c[nt][0] = c[nt][1] = c[nt][2] = c[nt][3] = 0.f;
        uint4 kv = *(const uint4*)(kg + (8 * nt + gid) * 32 + 8 * tig);
        mma_f16(c[nt], qi0.x, qi1.x, qi0.y, qi1.y, kv.x, kv.y);
        mma_f16(c[nt], qi0.z, qi1.z, qi0.w, qi1.w, kv.z, kv.w);
    }

    // ---- add fused mask+bias, row maxes ----
    float mx0 = -1e30f, mx1 = -1e30f;
#pragma unroll
    for (int nt = 0; nt < 8; nt++) {
        int coff = nt * 8 + 2 * tig;
        float2 m0 = *(const float2*)&smb[i0 * 68 + coff];
        float2 m1 = *(const float2*)&smb[i1 * 68 + coff];
        c[nt][0] += m0.x;
        c[nt][1] += m0.y;
        c[nt][2] += m1.x;
        c[nt][3] += m1.y;
        mx0 = fmaxf(mx0, fmaxf(c[nt][0], c[nt][1]));
        mx1 = fmaxf(mx1, fmaxf(c[nt][2], c[nt][3]));
    }
    mx0 = fmaxf(mx0, __shfl_xor_sync(~0u, mx0, 1));
    mx0 = fmaxf(mx0, __shfl_xor_sync(~0u, mx0, 2));
    mx1 = fmaxf(mx1, __shfl_xor_sync(~0u, mx1, 1));
    mx1 = fmaxf(mx1, __shfl_xor_sync(~0u, mx1, 2));

    float s0 = 0.f, s1 = 0.f;
#pragma unroll
    for (int nt = 0; nt < 8; nt++) {
        c[nt][0] = __expf(c[nt][0] - mx0);
        c[nt][1] = __expf(c[nt][1] - mx0);
        c[nt][2] = __expf(c[nt][2] - mx1);
        c[nt][3] = __expf(c[nt][3] - mx1);
        s0 += c[nt][0] + c[nt][1];
        s1 += c[nt][2] + c[nt][3];
    }
    s0 += __shfl_xor_sync(~0u, s0, 1);
    s0 += __shfl_xor_sync(~0u, s0, 2);
    s1 += __shfl_xor_sync(~0u, s1, 1);
    s1 += __shfl_xor_sync(~0u, s1, 2);
    float r0 = 1.0f / s0, r1 = 1.0f / s1;

    // ---- pack P rows into half2 ----
    unsigned h01[8], h23[8];
#pragma unroll
    for (int nt = 0; nt < 8; nt++) {
        h01[nt] = pack_h2(c[nt][0] * r0, c[nt][1] * r0);
        h23[nt] = pack_h2(c[nt][2] * r1, c[nt][3] * r1);
    }

    // ---- O = P.V ----
    const int sA = (gid << 2) + 2 * (tig & 1);
    const int sB = sA + 1;
    const bool hi = (tig & 2) != 0;

    float co[4][4];
#pragma unroll
    for (int dt = 0; dt < 4; dt++)
        co[dt][0] = co[dt][1] = co[dt][2] = co[dt][3] = 0.f;

#pragma unroll
    for (int g = 0; g < 4; g++) {
        unsigned uA0 = __shfl_sync(~0u, h01[2 * g],     sA);
        unsigned uA1 = __shfl_sync(~0u, h01[2 * g + 1], sA);
        unsigned uB0 = __shfl_sync(~0u, h01[2 * g],     sB);
        unsigned uB1 = __shfl_sync(~0u, h01[2 * g + 1], sB);
        unsigned vA0 = __shfl_sync(~0u, h23[2 * g],     sA);
        unsigned vA1 = __shfl_sync(~0u, h23[2 * g + 1], sA);
        unsigned vB0 = __shfl_sync(~0u, h23[2 * g],     sB);
        unsigned vB1 = __shfl_sync(~0u, h23[2 * g + 1], sB);
        unsigned a0 = hi ? uA1 : uA0;
        unsigned a1 = hi ? vA1 : vA0;
        unsigned a2 = hi ? uB1 : uB0;
        unsigned a3 = hi ? vB1 : vB0;
#pragma unroll
        for (int dt = 0; dt < 4; dt++) {
            uint2 vv = *(const uint2*)(vg + (8 * dt + gid) * 64 + 16 * g + 4 * tig);
            mma_f16(co[dt], a0, a1, a2, a3, vv.x, vv.y);
        }
    }

    // ---- store O as fp16: g_oh[m][h*32 + d] ----
    size_t orow0 = ((size_t)(b * 64 + i0)) * CDIM + h * 32;
    size_t orow1 = ((size_t)(b * 64 + i1)) * CDIM + h * 32;
#pragma unroll
    for (int dt = 0; dt < 4; dt++) {
        int col = dt * 8 + 2 * tig;
        *(__half2*)&g_oh[orow0 + col] = __floats2half2_rn(co[dt][0], co[dt][1]);
        *(__half2*)&g_oh[orow1 + col] = __floats2half2_rn(co[dt][2], co[dt][3]);
    }
}

// ---------------- launch ----------------
extern "C" void kernel_launch(void* const* d_in, const int* in_sizes, int n_in,
                              void* d_out, int out_size)
{
    const float* x          = (const float*)d_in[0];
    const float* mask       = (const float*)d_in[1];
    const float* Wq         = (const float*)d_in[2];
    const float* bq         = (const float*)d_in[3];
    const float* Wkv        = (const float*)d_in[4];
    const float* bkv        = (const float*)d_in[5];
    const float* bias_table = (const float*)d_in[6];
    const float* Wp         = (const float*)d_in[7];
    const float* bp         = (const float*)d_in[8];
    float* out = (float*)d_out;

    conv_x<<<MROWS * CDIM / 4 / 256, 256>>>(x);
    round_w<<<256, 256>>>(Wq, Wkv, Wp);
    bias8_kernel<<<128, 256>>>(bias_table);
    mma_gemm<0><<<dim3(6, MROWS / 128), 256>>>(bq, bkv, nullptr);
    attn_kernel<<<BWIN * HEADS, 128>>>(mask);
    mma_gemm<1><<<dim3(2, MROWS / 128), 256>>>(bp, nullptr, out);
}